// round 15
// baseline (speedup 1.0000x reference)
#include <cuda_runtime.h>
#include <cuda_fp16.h>
#include <cstdint>

#define NTOT   262144
#define NTILES 16384                    // 16 n per tile
#define SCALE  0.14433756729740643f

// A row (pitch 304B = 19 units, XOR-1 unit swizzle per 8-row group):
//   units 0..6 = xh (d*2), 7..9 pad; units 10..16 = xl (160+d*2), 17..18 pad
#define OFF_A   0                       // 64 x 304B = 19456
// T planes: pitch 144B = 9 units/row; plane0 = cols 8g..8g+3, plane1 = 8g+4..8g+7
#define OFF_P0  19456                   // 64 x 144 = 9216
#define OFF_P1  28672                   // 9216
#define OFF_OS  OFF_P0                  // out stage aliases planes (14336 <= 18432)
#define OFF_AP  37888                   // probs 16n x 4s x float4 = 1024
#define OFF_SB  38912                   // bias 64 f32
#define SMEM_USED 39168
#define SMEM_TOTAL (SMEM_USED + 1024)

// B fragments: [strip(7)][ks(8: 4 wh + 4 wl)][lane(32)] -> uint4 (28 KB)
__device__ uint4 g_Bfrag[7 * 8 * 32];

__device__ __forceinline__ float foldw(int j, int d,
                                       const float* wq, const float* wk,
                                       const float* wv, const float* wfc) {
    if (d >= 55) return 0.f;
    if (j < 55) {
        float s = 0.f;
        #pragma unroll 8
        for (int e = 0; e < 48; e++) s += wq[e * 55 + d] * wk[e * 55 + j];
        return s * SCALE;
    }
    if (j >= 56 && j < 111) {
        int dd = j - 56;
        float s = 0.f;
        #pragma unroll 8
        for (int e = 0; e < 48; e++) s += wv[e * 55 + d] * wfc[dd * 48 + e];
        return s;
    }
    return 0.f;
}
__device__ __forceinline__ uint32_t pack2(float w0, float w1, bool lo) {
    __half h0 = __float2half_rn(w0), h1 = __float2half_rn(w1);
    __half o0 = lo ? __float2half_rn(w0 - __half2float(h0)) : h0;
    __half o1 = lo ? __float2half_rn(w1 - __half2float(h1)) : h1;
    return (uint32_t)__half_as_ushort(o0) | ((uint32_t)__half_as_ushort(o1) << 16);
}

__global__ void prep_kernel(const float* __restrict__ wq, const float* __restrict__ wk,
                            const float* __restrict__ wv, const float* __restrict__ wfc) {
    int idx = blockIdx.x * 256 + threadIdx.x;
    if (idx >= 7 * 8 * 32) return;
    int lane  = idx & 31;
    int ks    = (idx >> 5) & 7;
    int strip = idx >> 8;
    bool lo   = ks >= 4;
    int kb    = (lo ? ks - 4 : ks) * 16 + 2 * (lane & 3);
    int r     = strip * 16 + (lane >> 2);
    uint4 v;
    v.x = pack2(foldw(r,     kb,     wq,wk,wv,wfc), foldw(r,     kb + 1, wq,wk,wv,wfc), lo);
    v.y = pack2(foldw(r,     kb + 8, wq,wk,wv,wfc), foldw(r,     kb + 9, wq,wk,wv,wfc), lo);
    v.z = pack2(foldw(r + 8, kb,     wq,wk,wv,wfc), foldw(r + 8, kb + 1, wq,wk,wv,wfc), lo);
    v.w = pack2(foldw(r + 8, kb + 8, wq,wk,wv,wfc), foldw(r + 8, kb + 9, wq,wk,wv,wfc), lo);
    g_Bfrag[idx] = v;
}

__device__ __forceinline__ uint32_t s2u(const void* p) {
    uint32_t a;
    asm("{ .reg .u64 t; cvta.to.shared.u64 t, %1; cvt.u32.u64 %0, t; }" : "=r"(a) : "l"(p));
    return a;
}
__device__ __forceinline__ void ldsm4(uint32_t* r, uint32_t addr) {
    asm volatile("ldmatrix.sync.aligned.m8n8.x4.shared.b16 {%0,%1,%2,%3}, [%4];"
                 : "=r"(r[0]), "=r"(r[1]), "=r"(r[2]), "=r"(r[3]) : "r"(addr));
}
__device__ __forceinline__ void mma16816(float* c, const uint32_t* a, uint32_t b0, uint32_t b1) {
    asm volatile("mma.sync.aligned.m16n8k16.row.col.f32.f16.f16.f32 "
                 "{%0,%1,%2,%3}, {%4,%5,%6,%7}, {%8,%9}, {%0,%1,%2,%3};"
                 : "+f"(c[0]), "+f"(c[1]), "+f"(c[2]), "+f"(c[3])
                 : "r"(a[0]), "r"(a[1]), "r"(a[2]), "r"(a[3]), "r"(b0), "r"(b1));
}
__device__ __forceinline__ float2 h2f2(uint32_t u) {
    return __half22float2(*(__half2*)&u);
}

__global__ __launch_bounds__(128, 5) void mha_kernel(const float* __restrict__ x,
                                                     const float* __restrict__ bfc,
                                                     float* __restrict__ out) {
    extern __shared__ char smraw[];
    uint32_t sb0 = s2u(smraw);
    uint32_t sb  = (sb0 + 1023u) & ~1023u;
    char* sm = smraw + (sb - sb0);

    const int tid  = threadIdx.x;
    const int wid  = tid >> 5;
    const int lane = tid & 31;

    for (int i = tid; i < 19456 / 4; i += 128)     // zero A once (pads persist)
        *(uint32_t*)(sm + OFF_A + i * 4) = 0u;
    for (int i = tid; i < (2 * 9216) / 4; i += 128) // zero planes (g7/pad persist except OS alias)
        *(uint32_t*)(sm + OFF_P0 + i * 4) = 0u;
    for (int i = tid; i < 64; i += 128)
        *(float*)(sm + OFF_SB + i * 4) = (i < 55) ? bfc[i] : 0.f;

    const int gid = lane >> 2, tig = lane & 3;
    const int town = gid & 3;
    const int R0  = wid * 16;
    const int arow = R0 + (lane & 15);
    const int hiSw = ((lane >> 4) & 1) ^ ((arow >> 3) & 1);
    const uint32_t aBaseH = sb + OFF_A + (uint32_t)arow * 304 + (uint32_t)hiSw * 16;
    const uint32_t aBaseL = aBaseH + 160;
    const int posS = (town >> 1) * 110 + (town & 1) * 5;
    // T-write plane base for this lane: plane by tig>>1, half-offset by tig&1
    char* const tw = sm + (tig < 2 ? OFF_P0 : OFF_P1) + (tig & 1) * 8;

    float* OS  = (float*)(sm + OFF_OS);
    float* APs = (float*)(sm + OFF_AP);
    const float* sB = (const float*)(sm + OFF_SB);
    const uint4* gb0 = g_Bfrag + lane;
    __syncthreads();

    for (int t = blockIdx.x; t < NTILES; t += gridDim.x) {
        // ---- scatter: gmem -> A (xh, xl half stores), swizzled; re-zero g7 slots ----
        {
            const float4* xin = (const float4*)(x + (size_t)t * 3520);
            #pragma unroll
            for (int i = 0; i < 7; i++) {
                int idx = tid + 128 * i;
                if (idx < 880) {
                    float4 v = xin[idx];
                    float vv[4] = {v.x, v.y, v.z, v.w};
                    int n_l = idx / 55;
                    int l0  = (idx - n_l * 55) * 4;
                    #pragma unroll
                    for (int jj = 0; jj < 4; jj++) {
                        int l  = l0 + jj;
                        int r  = l / 10, cc = l - r * 10;
                        int p1 = r / 11, h = r - p1 * 11;
                        int p2 = cc / 5, w = cc - p2 * 5;
                        int row = n_l * 4 + p1 * 2 + p2;
                        int d   = h * 5 + w;
                        float val = vv[jj];
                        __half hh = __float2half_rn(val);
                        __half hl = __float2half_rn(val - __half2float(hh));
                        int ph = (((d >> 3) ^ ((row >> 3) & 1)) << 4) + (d & 7) * 2;
                        char* rp = sm + OFF_A + row * 304;
                        *(__half*)(rp + ph)       = hh;
                        *(__half*)(rp + 160 + ph) = hl;
                    }
                }
            }
            // re-zero g=7 octet of both planes (OS alias clobbered them last iter)
            int rz = tid >> 1, pz = tid & 1;
            uint4 z = make_uint4(0u, 0u, 0u, 0u);
            *(uint4*)(sm + (pz ? OFF_P1 : OFF_P0) + rz * 144 + 7 * 16) = z;
        }
        __syncthreads();

        // ---- MMA: 7 strips x (4 ks wh x {xh,xl} + 4 ks wl x xh); T->planes, U->regs ----
        float Ureg[2][14];
        {
            uint32_t aFh[4][4], aFl[4][4];
            #pragma unroll
            for (int ks = 0; ks < 4; ks++) {
                ldsm4(aFh[ks], aBaseH + ks * 32);
                ldsm4(aFl[ks], aBaseL + ks * 32);
            }
            #pragma unroll
            for (int ntp = 0; ntp < 7; ntp++) {
                float acc[8];
                #pragma unroll
                for (int q = 0; q < 8; q++) acc[q] = 0.f;
                const uint4* gb = gb0 + ntp * 256;
                #pragma unroll
                for (int ks = 0; ks < 4; ks++) {            // wh x (xh + xl)
                    uint4 bf = __ldg(gb + ks * 32);
                    mma16816(acc,     aFh[ks], bf.x, bf.y);
                    mma16816(acc + 4, aFh[ks], bf.z, bf.w);
                    mma16816(acc,     aFl[ks], bf.x, bf.y);
                    mma16816(acc + 4, aFl[ks], bf.z, bf.w);
                }
                #pragma unroll
                for (int ks = 0; ks < 4; ks++) {            // wl x xh
                    uint4 bf = __ldg(gb + (4 + ks) * 32);
                    mma16816(acc,     aFh[ks], bf.x, bf.y);
                    mma16816(acc + 4, aFh[ks], bf.z, bf.w);
                }
                int r = R0 + gid;
                if (ntp <= 3) {                              // cols c0: g = 2*ntp
                    *(float2*)(tw + r * 144 + ntp * 32)       = make_float2(acc[0], acc[1]);
                    *(float2*)(tw + (r + 8) * 144 + ntp * 32) = make_float2(acc[2], acc[3]);
                }
                if (ntp <= 2) {                              // cols c0+8: g = 2*ntp+1
                    *(float2*)(tw + r * 144 + ntp * 32 + 16)       = make_float2(acc[4], acc[5]);
                    *(float2*)(tw + (r + 8) * 144 + ntp * 32 + 16) = make_float2(acc[6], acc[7]);
                }
                if (ntp == 3) {
                    Ureg[0][0] = acc[4]; Ureg[0][1] = acc[5];
                    Ureg[1][0] = acc[6]; Ureg[1][1] = acc[7];
                }
                if (ntp >= 4) {
                    int u0 = 2 + (ntp - 4) * 4;
                    Ureg[0][u0]     = acc[0]; Ureg[0][u0 + 1] = acc[1];
                    Ureg[1][u0]     = acc[2]; Ureg[1][u0 + 1] = acc[3];
                    Ureg[0][u0 + 2] = acc[4]; Ureg[0][u0 + 3] = acc[5];
                    Ureg[1][u0 + 2] = acc[6]; Ureg[1][u0 + 3] = acc[7];
                }
            }
        }
        __syncthreads();

        // ---- stage C: thread=(n, octet g); T/x each read once; shfl-tree reduce ----
        {
            int n8 = tid >> 3, g = tid & 7;
            // x octets for the 4 t-rows (xh + xl reconstruction)
            float xo[4][8];
            #pragma unroll
            for (int t4 = 0; t4 < 4; t4++) {
                int row = n8 * 4 + t4;
                int off = ((g ^ ((row >> 3) & 1)) << 4);
                const char* rp = sm + OFF_A + row * 304;
                uint4 xh = *(const uint4*)(rp + off);
                uint4 xl = *(const uint4*)(rp + 160 + off);
                #pragma unroll
                for (int m = 0; m < 4; m++) {
                    float2 fh = h2f2((&xh.x)[m]);
                    float2 fl = h2f2((&xl.x)[m]);
                    xo[t4][2 * m]     = fh.x + fl.x;
                    xo[t4][2 * m + 1] = fh.y + fl.y;
                }
            }
            float S16[16];
            #pragma unroll
            for (int s4 = 0; s4 < 4; s4++) {
                int row = n8 * 4 + s4;
                uint4 u0 = *(const uint4*)(sm + OFF_P0 + row * 144 + g * 16);
                uint4 u1 = *(const uint4*)(sm + OFF_P1 + row * 144 + g * 16);
                float tv[8];
                tv[0] = __uint_as_float(u0.x); tv[1] = __uint_as_float(u0.y);
                tv[2] = __uint_as_float(u0.z); tv[3] = __uint_as_float(u0.w);
                tv[4] = __uint_as_float(u1.x); tv[5] = __uint_as_float(u1.y);
                tv[6] = __uint_as_float(u1.z); tv[7] = __uint_as_float(u1.w);
                #pragma unroll
                for (int t4 = 0; t4 < 4; t4++) {
                    float a = 0.f;
                    #pragma unroll
                    for (int k = 0; k < 8; k++) a += tv[k] * xo[t4][k];
                    S16[s4 * 4 + t4] = a;
                }
            }
            // reduce over g: xor4, xor2, xor1 (keep-half)
            float S8[8];
            #pragma unroll
            for (int j = 0; j < 8; j++) {
                float send = (g & 4) ? S16[j] : S16[j + 8];
                float keep = (g & 4) ? S16[j + 8] : S16[j];
                S8[j] = keep + __shfl_xor_sync(0xffffffffu, send, 4);
            }
            float S4v[4];
            #pragma unroll
            for (int j = 0; j < 4; j++) {
                float send = (g & 2) ? S8[j] : S8[j + 4];
                float keep = (g & 2) ? S8[j + 4] : S8[j];
                S4v[j] = keep + __shfl_xor_sync(0xffffffffu, send, 2);
            }
            float S2v[2];
            #pragma unroll
            for (int j = 0; j < 2; j++) {
                float send = (g & 1) ? S4v[j] : S4v[j + 2];
                float keep = (g & 1) ? S4v[j + 2] : S4v[j];
                S2v[j] = keep + __shfl_xor_sync(0xffffffffu, send, 1);
            }
            float o0 = __shfl_xor_sync(0xffffffffu, S2v[0], 1);
            float o1 = __shfl_xor_sync(0xffffffffu, S2v[1], 1);
            float t0, t1, t2, t3;
            if ((g & 1) == 0) { t0 = S2v[0]; t1 = S2v[1]; t2 = o0; t3 = o1; }
            else              { t0 = o0;     t1 = o1;     t2 = S2v[0]; t3 = S2v[1]; }
            float m = fmaxf(fmaxf(t0, t1), fmaxf(t2, t3));
            float e0 = __expf(t0 - m), e1 = __expf(t1 - m);
            float e2 = __expf(t2 - m), e3 = __expf(t3 - m);
            float inv = 1.f / (e0 + e1 + e2 + e3);
            if ((g & 1) == 0)
                *(float4*)(APs + (n8 * 4 + (g >> 1)) * 4) =
                    make_float4(e0 * inv, e1 * inv, e2 * inv, e3 * inv);
        }
        __syncthreads();

        // ---- stage D: out = b + p*U (bias/pos computed per-u); OS overwrites planes ----
        {
            float q[2][4];
            int   ntv[2];
            #pragma unroll
            for (int rp = 0; rp < 2; rp++) {
                int row = R0 + gid + 8 * rp;
                int nt  = row >> 2;
                ntv[rp] = nt;
                int ab  = (nt * 4 + town) * 4;
                q[rp][0] = APs[ab + town];
                q[rp][1] = APs[ab + (town ^ 1)];
                q[rp][2] = APs[ab + (town ^ 2)];
                q[rp][3] = APs[ab + (town ^ 3)];
            }
            #pragma unroll
            for (int u = 0; u < 14; u++) {
                int d;
                if (u < 2) d = 2 * tig + u;
                else {
                    int iu = u - 2;
                    int g2 = iu >> 2, r4 = iu & 3;
                    d = 8 + 16 * g2 + 2 * tig + (r4 >> 1) * 8 + (r4 & 1);
                }
                bool valid = (d < 55);
                int dc  = valid ? d : 0;
                int pos = (dc / 5) * 10 + (dc % 5) + posS;
                float bias = sB[dc];
                #pragma unroll
                for (int rp = 0; rp < 2; rp++) {
                    float own = Ureg[rp][u];
                    float ua = __shfl_xor_sync(0xffffffffu, own, 4);
                    float ub = __shfl_xor_sync(0xffffffffu, own, 8);
                    float uc = __shfl_xor_sync(0xffffffffu, own, 12);
                    float o = bias + q[rp][0] * own + q[rp][1] * ua
                                   + q[rp][2] * ub  + q[rp][3] * uc;
                    if (valid)
                        OS[ntv[rp] * 224 + pos] = o;
                }
            }
        }
        __syncthreads();

        // ---- coalesced store OS -> gmem ----
        {
            float* gout = out + (size_t)t * 3520;
            #pragma unroll
            for (int i = 0; i < 7; i++) {
                int idx = tid + 128 * i;
                if (idx < 880) {
                    int n = idx / 55, jj = idx - n * 55;
                    *(float4*)(gout + n * 220 + jj * 4) =
                        *(const float4*)(OS + n * 224 + jj * 4);
                }
            }
        }
        __syncthreads();
    }
}

extern "C" void kernel_launch(void* const* d_in, const int* in_sizes, int n_in,
                              void* d_out, int out_size) {
    const float* x   = (const float*)d_in[0];
    const float* wq  = (const float*)d_in[1];
    const float* wk  = (const float*)d_in[2];
    const float* wv  = (const float*)d_in[3];
    const float* wfc = (const float*)d_in[4];
    const float* bfc = (const float*)d_in[5];
    float* out = (float*)d_out;

    int nsm = 148;
    cudaDeviceGetAttribute(&nsm, cudaDevAttrMultiProcessorCount, 0);

    cudaFuncSetAttribute(mha_kernel, cudaFuncAttributeMaxDynamicSharedMemorySize, SMEM_TOTAL);
    prep_kernel<<<7, 256>>>(wq, wk, wv, wfc);
    mha_kernel<<<nsm * 5, 128, SMEM_TOTAL>>>(x, bfc, out);
}

// round 16
// speedup vs baseline: 1.0510x; 1.0510x over previous
#include <cuda_runtime.h>
#include <cuda_fp16.h>
#include <cuda_fp8.h>
#include <cstdint>

#define NTOT   262144
#define NTILES 16384                    // 16 n per tile
#define SCALE  0.14433756729740643f
#define WLSC   16384.0f                 // 2^14 wl pre-scale
#define WLINV  6.103515625e-05f         // 2^-14

// A row layout (pitch 304B = 19 x 16B units, XOR-1 swizzle on unit index per 8-row group):
//   units 0..6 : xh halves (d*2), 7..9 pad; units 10..16: xl halves (160+d*2), 17..18 pad
#define OFF_A   0                       // 64 rows x 304B = 19456
#define OFF_T   19456                   // 64 rows x 232B (58-word pitch)
#define OFF_OS  OFF_T                   // out stage aliases T (14336 <= 14848)
#define OFF_AP  34304                   // probs 16 n x 4 s x float4 = 1024
#define OFF_SB  35328                   // bias table 64 f32 = 256
#define SMEM_USED 35584
#define SMEM_TOTAL (SMEM_USED + 1024)

// wh fragments: [strip(7)][ks(4)][lane(32)] -> uint4 (14 KB)
__device__ uint4 g_Bfrag[7 * 4 * 32];
// wl fragments (e4m3, x 2^14): [strip(7)][ks(4)][lane(32)] -> uint2 (7 KB)
__device__ uint2 g_Bfrag8[7 * 4 * 32];

__device__ __forceinline__ float foldw(int j, int d,
                                       const float* wq, const float* wk,
                                       const float* wv, const float* wfc) {
    if (d >= 55) return 0.f;
    if (j < 55) {
        float s = 0.f;
        #pragma unroll 8
        for (int e = 0; e < 48; e++) s += wq[e * 55 + d] * wk[e * 55 + j];
        return s * SCALE;
    }
    if (j >= 56 && j < 111) {
        int dd = j - 56;
        float s = 0.f;
        #pragma unroll 8
        for (int e = 0; e < 48; e++) s += wv[e * 55 + d] * wfc[dd * 48 + e];
        return s;
    }
    return 0.f;
}
__device__ __forceinline__ uint32_t packh2(float w0, float w1) {
    __half h0 = __float2half_rn(w0), h1 = __float2half_rn(w1);
    return (uint32_t)__half_as_ushort(h0) | ((uint32_t)__half_as_ushort(h1) << 16);
}
__device__ __forceinline__ uint8_t wl8(int j, int d,
                                       const float* wq, const float* wk,
                                       const float* wv, const float* wfc) {
    float w  = foldw(j, d, wq, wk, wv, wfc);
    float wl = (w - __half2float(__float2half_rn(w))) * WLSC;
    return (uint8_t)__nv_cvt_float_to_fp8(wl, __NV_SATFINITE, __NV_E4M3);
}

__global__ void prep_kernel(const float* __restrict__ wq, const float* __restrict__ wk,
                            const float* __restrict__ wv, const float* __restrict__ wfc) {
    int idx = blockIdx.x * 256 + threadIdx.x;
    if (idx >= 7 * 4 * 32 * 2) return;
    int half2nd = idx >= 7 * 4 * 32;
    int i     = idx - half2nd * (7 * 4 * 32);
    int lane  = i & 31;
    int ks    = (i >> 5) & 3;
    int strip = i >> 7;
    int kb    = ks * 16 + 2 * (lane & 3);
    int r     = strip * 16 + (lane >> 2);
    if (!half2nd) {
        uint4 v;
        v.x = packh2(foldw(r,     kb,     wq,wk,wv,wfc), foldw(r,     kb + 1, wq,wk,wv,wfc));
        v.y = packh2(foldw(r,     kb + 8, wq,wk,wv,wfc), foldw(r,     kb + 9, wq,wk,wv,wfc));
        v.z = packh2(foldw(r + 8, kb,     wq,wk,wv,wfc), foldw(r + 8, kb + 1, wq,wk,wv,wfc));
        v.w = packh2(foldw(r + 8, kb + 8, wq,wk,wv,wfc), foldw(r + 8, kb + 9, wq,wk,wv,wfc));
        g_Bfrag[i] = v;
    } else {
        uint2 v;
        v.x = (uint32_t)wl8(r, kb,     wq,wk,wv,wfc)
            | ((uint32_t)wl8(r, kb + 1, wq,wk,wv,wfc) << 8)
            | ((uint32_t)wl8(r, kb + 8, wq,wk,wv,wfc) << 16)
            | ((uint32_t)wl8(r, kb + 9, wq,wk,wv,wfc) << 24);
        v.y = (uint32_t)wl8(r + 8, kb,     wq,wk,wv,wfc)
            | ((uint32_t)wl8(r + 8, kb + 1, wq,wk,wv,wfc) << 8)
            | ((uint32_t)wl8(r + 8, kb + 8, wq,wk,wv,wfc) << 16)
            | ((uint32_t)wl8(r + 8, kb + 9, wq,wk,wv,wfc) << 24);
        g_Bfrag8[i] = v;
    }
}

__device__ __forceinline__ uint32_t s2u(const void* p) {
    uint32_t a;
    asm("{ .reg .u64 t; cvta.to.shared.u64 t, %1; cvt.u32.u64 %0, t; }" : "=r"(a) : "l"(p));
    return a;
}
__device__ __forceinline__ void ldsm4(uint32_t* r, uint32_t addr) {
    asm volatile("ldmatrix.sync.aligned.m8n8.x4.shared.b16 {%0,%1,%2,%3}, [%4];"
                 : "=r"(r[0]), "=r"(r[1]), "=r"(r[2]), "=r"(r[3]) : "r"(addr));
}
__device__ __forceinline__ void mma16816(float* c, const uint32_t* a, uint32_t b0, uint32_t b1) {
    asm volatile("mma.sync.aligned.m16n8k16.row.col.f32.f16.f16.f32 "
                 "{%0,%1,%2,%3}, {%4,%5,%6,%7}, {%8,%9}, {%0,%1,%2,%3};"
                 : "+f"(c[0]), "+f"(c[1]), "+f"(c[2]), "+f"(c[3])
                 : "r"(a[0]), "r"(a[1]), "r"(a[2]), "r"(a[3]), "r"(b0), "r"(b1));
}
__device__ __forceinline__ uint32_t cvt8(uint32_t v) {   // low 16 bits: 2 e4m3 -> f16x2
    uint32_t r;
    asm("cvt.rn.f16x2.e4m3x2 %0, %1;" : "=r"(r) : "h"((uint16_t)v));
    return r;
}
__device__ __forceinline__ float2 h2f2(uint32_t u) {
    return __half22float2(*(__half2*)&u);
}

__global__ __launch_bounds__(128, 5) void mha_kernel(const float* __restrict__ x,
                                                     const float* __restrict__ bfc,
                                                     float* __restrict__ out) {
    extern __shared__ char smraw[];
    uint32_t sb0 = s2u(smraw);
    uint32_t sb  = (sb0 + 1023u) & ~1023u;
    char* sm = smraw + (sb - sb0);

    const int tid  = threadIdx.x;
    const int wid  = tid >> 5;
    const int lane = tid & 31;

    for (int i = tid; i < 19456 / 4; i += 128)     // zero A once (pads persist)
        *(uint32_t*)(sm + OFF_A + i * 4) = 0u;
    for (int i = tid; i < 64; i += 128)
        *(float*)(sm + OFF_SB + i * 4) = (i < 55) ? bfc[i] : 0.f;

    const int gid = lane >> 2, tig = lane & 3;
    const int town = gid & 3;
    const int R0  = wid * 16;
    const int arow = R0 + (lane & 15);
    const int hiSw = ((lane >> 4) & 1) ^ ((arow >> 3) & 1);
    const uint32_t aBaseH = sb + OFF_A + (uint32_t)arow * 304 + (uint32_t)hiSw * 16;
    const uint32_t aBaseL = aBaseH + 160;
    const int posS = (town >> 1) * 110 + (town & 1) * 5;

    float* Tf  = (float*)(sm + OFF_T);
    float* OS  = (float*)(sm + OFF_OS);
    float* APs = (float*)(sm + OFF_AP);
    const float* sB = (const float*)(sm + OFF_SB);
    const uint4* gb0  = g_Bfrag  + lane;
    const uint2* gb8  = g_Bfrag8 + lane;
    __syncthreads();

    for (int t = blockIdx.x; t < NTILES; t += gridDim.x) {
        // ---- scatter: gmem -> A, two half stores (xh, xl) per element, swizzled ----
        {
            const float4* xin = (const float4*)(x + (size_t)t * 3520);
            #pragma unroll
            for (int i = 0; i < 7; i++) {
                int idx = tid + 128 * i;
                if (idx < 880) {
                    float4 v = xin[idx];
                    float vv[4] = {v.x, v.y, v.z, v.w};
                    int n_l = idx / 55;
                    int l0  = (idx - n_l * 55) * 4;
                    #pragma unroll
                    for (int jj = 0; jj < 4; jj++) {
                        int l  = l0 + jj;
                        int r  = l / 10, cc = l - r * 10;
                        int p1 = r / 11, h = r - p1 * 11;
                        int p2 = cc / 5, w = cc - p2 * 5;
                        int row = n_l * 4 + p1 * 2 + p2;
                        int d   = h * 5 + w;
                        float val = vv[jj];
                        __half hh = __float2half_rn(val);
                        __half hl = __float2half_rn(val - __half2float(hh));
                        int ph = (((d >> 3) ^ ((row >> 3) & 1)) << 4) + (d & 7) * 2;
                        char* rp = sm + OFF_A + row * 304;
                        *(__half*)(rp + ph)       = hh;
                        *(__half*)(rp + 160 + ph) = hl;
                    }
                }
            }
        }
        __syncthreads();

        // ---- MMA: per strip: wl(fp8) pass first, scale acc by 2^-14, then wh passes ----
        float Ureg[2][14];
        {
            uint32_t aFh[4][4], aFl[4][4];
            #pragma unroll
            for (int ks = 0; ks < 4; ks++) {
                ldsm4(aFh[ks], aBaseH + ks * 32);
                ldsm4(aFl[ks], aBaseL + ks * 32);
            }
            #pragma unroll
            for (int ntp = 0; ntp < 7; ntp++) {
                float acc[8];
                #pragma unroll
                for (int q = 0; q < 8; q++) acc[q] = 0.f;
                const uint4* gb  = gb0 + ntp * 128;
                const uint2* g8  = gb8 + ntp * 128;
                #pragma unroll
                for (int ks = 0; ks < 4; ks++) {            // wl(x2^14) x xh  -> acc
                    uint2 bq = __ldg(g8 + ks * 32);
                    uint32_t b0 = cvt8(bq.x), b1 = cvt8(bq.x >> 16);
                    uint32_t b2 = cvt8(bq.y), b3 = cvt8(bq.y >> 16);
                    mma16816(acc,     aFh[ks], b0, b1);
                    mma16816(acc + 4, aFh[ks], b2, b3);
                }
                #pragma unroll
                for (int q = 0; q < 8; q++) acc[q] *= WLINV;   // undo 2^14
                #pragma unroll
                for (int ks = 0; ks < 4; ks++) {            // wh x (xh + xl)
                    uint4 bf = __ldg(gb + ks * 32);
                    mma16816(acc,     aFh[ks], bf.x, bf.y);
                    mma16816(acc + 4, aFh[ks], bf.z, bf.w);
                    mma16816(acc,     aFl[ks], bf.x, bf.y);
                    mma16816(acc + 4, aFl[ks], bf.z, bf.w);
                }
                int c0 = ntp * 16 + 2 * tig;
                int r  = R0 + gid;
                if (ntp <= 3) {
                    *(float2*)(Tf + r * 58 + c0)       = make_float2(acc[0], acc[1]);
                    *(float2*)(Tf + (r + 8) * 58 + c0) = make_float2(acc[2], acc[3]);
                }
                if (ntp <= 2) {
                    *(float2*)(Tf + r * 58 + c0 + 8)       = make_float2(acc[4], acc[5]);
                    *(float2*)(Tf + (r + 8) * 58 + c0 + 8) = make_float2(acc[6], acc[7]);
                }
                if (ntp == 3) {
                    Ureg[0][0] = acc[4]; Ureg[0][1] = acc[5];
                    Ureg[1][0] = acc[6]; Ureg[1][1] = acc[7];
                }
                if (ntp >= 4) {
                    int u0 = 2 + (ntp - 4) * 4;
                    Ureg[0][u0]     = acc[0]; Ureg[0][u0 + 1] = acc[1];
                    Ureg[1][u0]     = acc[2]; Ureg[1][u0 + 1] = acc[3];
                    Ureg[0][u0 + 2] = acc[4]; Ureg[0][u0 + 3] = acc[5];
                    Ureg[1][u0 + 2] = acc[6]; Ureg[1][u0 + 3] = acc[7];
                }
            }
        }
        __syncthreads();

        // ---- stage C: S = T x^T + softmax; x = xh + xl from swizzled A ----
        {
            int nl = tid >> 3;
            int s4 = (tid >> 1) & 3;
            int tp = tid & 1;
            const float* tr = Tf + (nl * 4 + s4) * 58;
            int xr0 = nl * 4 + 2 * tp;
            int sz  = (xr0 >> 3) & 1;
            const char* xa = sm + OFF_A + xr0 * 304;
            const char* xb = xa + 304;
            float sv0 = 0.f, sv1 = 0.f;
            #pragma unroll
            for (int u = 0; u < 7; u++) {
                int off = (u ^ sz) << 4;
                uint4 ha = *(const uint4*)(xa + off);
                uint4 la = *(const uint4*)(xa + 160 + off);
                uint4 hb = *(const uint4*)(xb + off);
                uint4 lb = *(const uint4*)(xb + 160 + off);
                #pragma unroll
                for (int m = 0; m < 4; m++) {
                    float2 tv = *(const float2*)(tr + 8 * u + 2 * m);
                    float2 fa = h2f2((&ha.x)[m]), ga = h2f2((&la.x)[m]);
                    float2 fb = h2f2((&hb.x)[m]), gb2 = h2f2((&lb.x)[m]);
                    sv0 += tv.x * (fa.x + ga.x) + tv.y * (fa.y + ga.y);
                    sv1 += tv.x * (fb.x + gb2.x) + tv.y * (fb.y + gb2.y);
                }
            }
            float o0 = __shfl_xor_sync(0xffffffffu, sv0, 1);
            float o1 = __shfl_xor_sync(0xffffffffu, sv1, 1);
            float t0, t1, t2, t3;
            if (tp == 0) { t0 = sv0; t1 = sv1; t2 = o0; t3 = o1; }
            else         { t0 = o0;  t1 = o1;  t2 = sv0; t3 = sv1; }
            float m = fmaxf(fmaxf(t0, t1), fmaxf(t2, t3));
            float e0 = __expf(t0 - m), e1 = __expf(t1 - m);
            float e2 = __expf(t2 - m), e3 = __expf(t3 - m);
            float inv = 1.f / (e0 + e1 + e2 + e3);
            if (tp == 0)
                *(float4*)(APs + (nl * 4 + s4) * 4) =
                    make_float4(e0 * inv, e1 * inv, e2 * inv, e3 * inv);
        }
        __syncthreads();

        // ---- stage D: out = b + p*U; bias/pos computed per-u ----
        {
            float q[2][4];
            int   ntv[2];
            #pragma unroll
            for (int rp = 0; rp < 2; rp++) {
                int row = R0 + gid + 8 * rp;
                int nt  = row >> 2;
                ntv[rp] = nt;
                int ab  = (nt * 4 + town) * 4;
                q[rp][0] = APs[ab + town];
                q[rp][1] = APs[ab + (town ^ 1)];
                q[rp][2] = APs[ab + (town ^ 2)];
                q[rp][3] = APs[ab + (town ^ 3)];
            }
            #pragma unroll
            for (int u = 0; u < 14; u++) {
                int d;
                if (u < 2) d = 2 * tig + u;
                else {
                    int iu = u - 2;
                    int g2 = iu >> 2, r4 = iu & 3;
                    d = 8 + 16 * g2 + 2 * tig + (r4 >> 1) * 8 + (r4 & 1);
                }
                bool valid = (d < 55);
                int dc  = valid ? d : 0;
                int pos = (dc / 5) * 10 + (dc % 5) + posS;
                float bias = sB[dc];
                #pragma unroll
                for (int rp = 0; rp < 2; rp++) {
                    float own = Ureg[rp][u];
                    float ua = __shfl_xor_sync(0xffffffffu, own, 4);
                    float ub = __shfl_xor_sync(0xffffffffu, own, 8);
                    float uc = __shfl_xor_sync(0xffffffffu, own, 12);
                    float o = bias + q[rp][0] * own + q[rp][1] * ua
                                   + q[rp][2] * ub  + q[rp][3] * uc;
                    if (valid)
                        OS[ntv[rp] * 224 + pos] = o;
                }
            }
        }
        __syncthreads();

        // ---- coalesced store OS -> gmem ----
        {
            float* gout = out + (size_t)t * 3520;
            #pragma unroll
            for (int i = 0; i < 7; i++) {
                int idx = tid + 128 * i;
                if (idx < 880) {
                    int n = idx / 55, jj = idx - n * 55;
                    *(float4*)(gout + n * 220 + jj * 4) =
                        *(const float4*)(OS + n * 224 + jj * 4);
                }
            }
        }
        __syncthreads();
    }
}

extern "C" void kernel_launch(void* const* d_in, const int* in_sizes, int n_in,
                              void* d_out, int out_size) {
    const float* x   = (const float*)d_in[0];
    const float* wq  = (const float*)d_in[1];
    const float* wk  = (const float*)d_in[2];
    const float* wv  = (const float*)d_in[3];
    const float* wfc = (const float*)d_in[4];
    const float* bfc = (const float*)d_in[5];
    float* out = (float*)d_out;

    int nsm = 148;
    cudaDeviceGetAttribute(&nsm, cudaDevAttrMultiProcessorCount, 0);

    cudaFuncSetAttribute(mha_kernel, cudaFuncAttributeMaxDynamicSharedMemorySize, SMEM_TOTAL);
    prep_kernel<<<7, 256>>>(wq, wk, wv, wfc);
    mha_kernel<<<nsm * 5, 128, SMEM_TOTAL>>>(x, bfc, out);
}